// round 4
// baseline (speedup 1.0000x reference)
#include <cuda_runtime.h>

#define DIMC   256
#define NHEADS 8
#define HDIM   32
#define MAXN   10048

// Scratch (no cudaMalloc allowed) — ~41 MB of __device__ globals.
__device__ float g_q[MAXN * DIMC];
__device__ float g_k[MAXN * DIMC];
__device__ float g_v[MAXN * DIMC];
__device__ float g_acc[MAXN * DIMC];

// ---------------------------------------------------------------------------
// Packed f32x2 helpers (Blackwell): 2 FMAs per issued instruction.
// ---------------------------------------------------------------------------
typedef unsigned long long u64t;

__device__ __forceinline__ u64t pack_dup(float x) {
    u64t r;
    asm("mov.b64 %0, {%1, %1};" : "=l"(r) : "f"(x));
    return r;
}
__device__ __forceinline__ void ffma2(u64t& acc, u64t a, u64t b) {
    asm("fma.rn.f32x2 %0, %1, %2, %0;" : "+l"(acc) : "l"(a), "l"(b));
}
__device__ __forceinline__ float2 unpack2(u64t v) {
    float2 r;
    asm("mov.b64 {%0, %1}, %2;" : "=f"(r.x), "=f"(r.y) : "l"(v));
    return r;
}

// ---------------------------------------------------------------------------
// Zero the accumulator.
// ---------------------------------------------------------------------------
__global__ void __launch_bounds__(256) zero_acc_kernel(int n4) {
    int i = blockIdx.x * blockDim.x + threadIdx.x;
    float4 z = make_float4(0.f, 0.f, 0.f, 0.f);
    int stride = gridDim.x * blockDim.x;
    for (; i < n4; i += stride)
        reinterpret_cast<float4*>(g_acc)[i] = z;
}

// ---------------------------------------------------------------------------
// Tiled fp32 GEMM with packed f32x2 FMA:
//   C[m][n] = sum_k X[m][k] * W[n][k] + bias[n]
// BM=64, BN=128, BK=16, 256 threads. Per thread: 4 rows (2 row-pairs) x 8 cols.
// Double-buffered smem.
// ---------------------------------------------------------------------------
#define BM 64
#define BN 128
#define BK 16

__device__ __forceinline__ void gemm_tile(
    const float* __restrict__ X, int M,
    const float* __restrict__ W,
    const float* __restrict__ Bv,
    float* __restrict__ C,
    int m0, int n0)
{
    __shared__ float As[2][BK][BM];
    __shared__ float Bs[2][BK][BN];

    int tid = threadIdx.x;
    int tx = tid & 15;           // 0..15 -> output cols tx*8
    int ty = tid >> 4;           // 0..15 -> output rows ty*4
    int lrow = tid >> 2;         // 0..63
    int lk   = (tid & 3) << 2;   // 0,4,8,12

    bool av = (m0 + lrow) < M;

    const float* Ap  = X + (size_t)(m0 + lrow) * DIMC + lk;
    const float* Bp0 = W + (size_t)(n0 + lrow) * DIMC + lk;
    const float* Bp1 = W + (size_t)(n0 + lrow + 64) * DIMC + lk;

    // acc2[p][j]: row-pair p (rows ty*4+2p, ty*4+2p+1), col tx*8+j. lo=row even.
    u64t acc2[2][8];
#pragma unroll
    for (int p = 0; p < 2; p++)
#pragma unroll
        for (int j = 0; j < 8; j++) acc2[p][j] = 0ull;

    const float4 zf4 = make_float4(0.f, 0.f, 0.f, 0.f);

    float4 ra  = av ? *reinterpret_cast<const float4*>(Ap) : zf4;
    float4 rb0 = *reinterpret_cast<const float4*>(Bp0);
    float4 rb1 = *reinterpret_cast<const float4*>(Bp1);

    int buf = 0;
    As[0][lk + 0][lrow] = ra.x;  As[0][lk + 1][lrow] = ra.y;
    As[0][lk + 2][lrow] = ra.z;  As[0][lk + 3][lrow] = ra.w;
    Bs[0][lk + 0][lrow] = rb0.x; Bs[0][lk + 1][lrow] = rb0.y;
    Bs[0][lk + 2][lrow] = rb0.z; Bs[0][lk + 3][lrow] = rb0.w;
    Bs[0][lk + 0][lrow + 64] = rb1.x; Bs[0][lk + 1][lrow + 64] = rb1.y;
    Bs[0][lk + 2][lrow + 64] = rb1.z; Bs[0][lk + 3][lrow + 64] = rb1.w;
    __syncthreads();

    const int NK = DIMC / BK;   // 16
#pragma unroll 1
    for (int kc = 0; kc < NK; kc++) {
        if (kc + 1 < NK) {
            int ko = (kc + 1) * BK;
            ra  = av ? *reinterpret_cast<const float4*>(Ap + ko) : zf4;
            rb0 = *reinterpret_cast<const float4*>(Bp0 + ko);
            rb1 = *reinterpret_cast<const float4*>(Bp1 + ko);
        }

#pragma unroll
        for (int kk = 0; kk < BK; kk++) {
            // A row-pairs: 4 consecutive floats = 2 packed pairs (16B load).
            ulonglong2 aw = *reinterpret_cast<const ulonglong2*>(&As[buf][kk][ty << 2]);
            u64t ap[2] = {aw.x, aw.y};
            float4 b0 = *reinterpret_cast<const float4*>(&Bs[buf][kk][tx << 3]);
            float4 b1 = *reinterpret_cast<const float4*>(&Bs[buf][kk][(tx << 3) + 4]);
            u64t bp[8];
            bp[0] = pack_dup(b0.x); bp[1] = pack_dup(b0.y);
            bp[2] = pack_dup(b0.z); bp[3] = pack_dup(b0.w);
            bp[4] = pack_dup(b1.x); bp[5] = pack_dup(b1.y);
            bp[6] = pack_dup(b1.z); bp[7] = pack_dup(b1.w);
#pragma unroll
            for (int p = 0; p < 2; p++)
#pragma unroll
                for (int j = 0; j < 8; j++)
                    ffma2(acc2[p][j], ap[p], bp[j]);
        }

        if (kc + 1 < NK) {
            int nb = buf ^ 1;
            As[nb][lk + 0][lrow] = ra.x;  As[nb][lk + 1][lrow] = ra.y;
            As[nb][lk + 2][lrow] = ra.z;  As[nb][lk + 3][lrow] = ra.w;
            Bs[nb][lk + 0][lrow] = rb0.x; Bs[nb][lk + 1][lrow] = rb0.y;
            Bs[nb][lk + 2][lrow] = rb0.z; Bs[nb][lk + 3][lrow] = rb0.w;
            Bs[nb][lk + 0][lrow + 64] = rb1.x; Bs[nb][lk + 1][lrow + 64] = rb1.y;
            Bs[nb][lk + 2][lrow + 64] = rb1.z; Bs[nb][lk + 3][lrow + 64] = rb1.w;
            __syncthreads();
            buf = nb;
        }
    }

    // Epilogue: bias + store. Rows ty*4 + (0..3), cols tx*8 + (0..7).
    float4 bb0 = *reinterpret_cast<const float4*>(Bv + n0 + (tx << 3));
    float4 bb1 = *reinterpret_cast<const float4*>(Bv + n0 + (tx << 3) + 4);
    float bbr[8] = {bb0.x, bb0.y, bb0.z, bb0.w, bb1.x, bb1.y, bb1.z, bb1.w};
#pragma unroll
    for (int p = 0; p < 2; p++) {
        float2 row0c[8], row1c[8];
#pragma unroll
        for (int j = 0; j < 8; j++) {
            float2 v = unpack2(acc2[p][j]);
            row0c[j].x = v.x;   // row 2p
            row1c[j].x = v.y;   // row 2p+1
        }
        int gm0 = m0 + (ty << 2) + (p << 1);
#pragma unroll
        for (int r = 0; r < 2; r++) {
            int gm = gm0 + r;
            if (gm < M) {
                float* cp = C + (size_t)gm * DIMC + n0 + (tx << 3);
                float4 o0, o1;
                if (r == 0) {
                    o0 = make_float4(row0c[0].x + bbr[0], row0c[1].x + bbr[1],
                                     row0c[2].x + bbr[2], row0c[3].x + bbr[3]);
                    o1 = make_float4(row0c[4].x + bbr[4], row0c[5].x + bbr[5],
                                     row0c[6].x + bbr[6], row0c[7].x + bbr[7]);
                } else {
                    o0 = make_float4(row1c[0].x + bbr[0], row1c[1].x + bbr[1],
                                     row1c[2].x + bbr[2], row1c[3].x + bbr[3]);
                    o1 = make_float4(row1c[4].x + bbr[4], row1c[5].x + bbr[5],
                                     row1c[6].x + bbr[6], row1c[7].x + bbr[7]);
                }
                *reinterpret_cast<float4*>(cp)     = o0;
                *reinterpret_cast<float4*>(cp + 4) = o1;
            }
        }
    }
}

__global__ void __launch_bounds__(256, 2) gemm_qkv_kernel(
    const float* __restrict__ X, int M,
    const float* __restrict__ Wq, const float* __restrict__ bq,
    const float* __restrict__ Wk, const float* __restrict__ bk,
    const float* __restrict__ Wv, const float* __restrict__ bv)
{
    const float* W; const float* B; float* C;
    int z = blockIdx.z;
    if (z == 0)      { W = Wq; B = bq; C = g_q; }
    else if (z == 1) { W = Wk; B = bk; C = g_k; }
    else             { W = Wv; B = bv; C = g_v; }
    gemm_tile(X, M, W, B, C, blockIdx.y * BM, blockIdx.x * BN);
}

__global__ void __launch_bounds__(256, 2) gemm_out_kernel(
    int M, const float* __restrict__ Wo, const float* __restrict__ bo,
    float* __restrict__ out)
{
    gemm_tile(g_acc, M, Wo, bo, out, blockIdx.y * BM, blockIdx.x * BN);
}

// ---------------------------------------------------------------------------
// Edge kernel: one warp per edge (unchanged this round).
// ---------------------------------------------------------------------------
__device__ __forceinline__ void red_add_v4(float* addr, float4 v) {
    asm volatile("red.global.add.v4.f32 [%0], {%1, %2, %3, %4};"
                 :: "l"(addr), "f"(v.x), "f"(v.y), "f"(v.z), "f"(v.w)
                 : "memory");
}

__global__ void __launch_bounds__(256) edge_kernel(
    const int* __restrict__ src, const int* __restrict__ dst, int E)
{
    int e = (blockIdx.x << 3) + (threadIdx.x >> 5);
    if (e >= E) return;
    int lane = threadIdx.x & 31;

    int s = src[e];
    int d = dst[e];

    const float4* qp = reinterpret_cast<const float4*>(g_q + (size_t)s * DIMC);
    const float4* kp = reinterpret_cast<const float4*>(g_k + (size_t)d * DIMC);

    float4 a0 = qp[lane];
    float4 a1 = qp[lane + 32];
    float4 b0 = kp[lane];
    float4 b1 = kp[lane + 32];

    float p0 = a0.x * b0.x + a0.y * b0.y + a0.z * b0.z + a0.w * b0.w;
    float p1 = a1.x * b1.x + a1.y * b1.y + a1.z * b1.z + a1.w * b1.w;

#pragma unroll
    for (int m = 1; m <= 4; m <<= 1) {
        p0 += __shfl_xor_sync(0xffffffffu, p0, m);
        p1 += __shfl_xor_sync(0xffffffffu, p1, m);
    }

    const float scale = 0.17677669529663687f;   // 1/sqrt(32)
    float sc0 = p0 * scale;
    float sc1 = p1 * scale;

    float sh[8];
#pragma unroll
    for (int h = 0; h < 4; h++) {
        sh[h]     = __shfl_sync(0xffffffffu, sc0, h << 3);
        sh[h + 4] = __shfl_sync(0xffffffffu, sc1, h << 3);
    }

    float mx = sh[0];
#pragma unroll
    for (int h = 1; h < 8; h++) mx = fmaxf(mx, sh[h]);
    float sum = 0.f;
#pragma unroll
    for (int h = 0; h < 8; h++) sum += expf(sh[h] - mx);
    float inv = 1.0f / sum;

    float w0 = expf(sc0 - mx) * inv;
    float w1 = expf(sc1 - mx) * inv;

    const float4* vp = reinterpret_cast<const float4*>(g_v + (size_t)s * DIMC);
    float4 v0 = vp[lane];
    float4 v1 = vp[lane + 32];

    float* op = g_acc + (size_t)d * DIMC;
    red_add_v4(op + (lane << 2),
               make_float4(v0.x * w0, v0.y * w0, v0.z * w0, v0.w * w0));
    red_add_v4(op + ((lane + 32) << 2),
               make_float4(v1.x * w1, v1.y * w1, v1.z * w1, v1.w * w1));
}

// ---------------------------------------------------------------------------
// Launch
// ---------------------------------------------------------------------------
extern "C" void kernel_launch(void* const* d_in, const int* in_sizes, int n_in,
                              void* d_out, int out_size)
{
    const float* x   = (const float*)d_in[0];
    const int*   src = (const int*)  d_in[1];
    const int*   dst = (const int*)  d_in[2];
    const float* Wq  = (const float*)d_in[3];
    const float* bq  = (const float*)d_in[4];
    const float* Wk  = (const float*)d_in[5];
    const float* bk  = (const float*)d_in[6];
    const float* Wv  = (const float*)d_in[7];
    const float* bv  = (const float*)d_in[8];
    const float* Wo  = (const float*)d_in[9];
    const float* bo  = (const float*)d_in[10];
    float* out = (float*)d_out;

    int N = in_sizes[0] / DIMC;
    int E = in_sizes[1];

    int mtiles = (N + BM - 1) / BM;

    // 1) zero accumulator
    int n4 = (N * DIMC) / 4;
    zero_acc_kernel<<<(n4 + 255) / 256, 256>>>(n4);

    // 2) Q/K/V projections (fused into one launch, z selects output)
    {
        dim3 grid(DIMC / BN, mtiles, 3);
        gemm_qkv_kernel<<<grid, 256>>>(x, N, Wq, bq, Wk, bk, Wv, bv);
    }

    // 3) per-edge attention + scatter
    edge_kernel<<<(E + 7) / 8, 256>>>(src, dst, E);

    // 4) output projection
    {
        dim3 grid(DIMC / BN, mtiles, 1);
        gemm_out_kernel<<<grid, 256>>>(N, Wo, bo, out);
    }
}

// round 5
// speedup vs baseline: 1.5290x; 1.5290x over previous
#include <cuda_runtime.h>
#include <cstdint>

#define DIMC   256
#define NHEADS 8
#define HDIM   32
#define MAXN   10048

// Scratch (no cudaMalloc allowed).
__device__ float g_q[MAXN * DIMC];
__device__ float g_k[MAXN * DIMC];
__device__ float g_v[MAXN * DIMC];
__device__ float g_acc[MAXN * DIMC];

// ---------------------------------------------------------------------------
// tf32 helpers
// ---------------------------------------------------------------------------
__device__ __forceinline__ uint32_t f2tf32(float x) {
    uint32_t r;
    asm("cvt.rna.tf32.f32 %0, %1;" : "=r"(r) : "f"(x));
    return r;
}

// (hi(x), hi(y), lo(x), lo(y)) all as tf32 bit patterns in float slots.
__device__ __forceinline__ float4 mk_hilo(float x, float y) {
    uint32_t hx = f2tf32(x), hy = f2tf32(y);
    float lx = x - __uint_as_float(hx);
    float ly = y - __uint_as_float(hy);
    return make_float4(__uint_as_float(hx), __uint_as_float(hy),
                       __uint_as_float(f2tf32(lx)), __uint_as_float(f2tf32(ly)));
}

__device__ __forceinline__ void mma_tf32(float* c,
    uint32_t a0, uint32_t a1, uint32_t a2, uint32_t a3,
    uint32_t b0, uint32_t b1)
{
    asm volatile(
        "mma.sync.aligned.m16n8k8.row.col.f32.tf32.tf32.f32 "
        "{%0,%1,%2,%3}, {%4,%5,%6,%7}, {%8,%9}, {%0,%1,%2,%3};"
        : "+f"(c[0]), "+f"(c[1]), "+f"(c[2]), "+f"(c[3])
        : "r"(a0), "r"(a1), "r"(a2), "r"(a3), "r"(b0), "r"(b1));
}

// ---------------------------------------------------------------------------
// Zero the accumulator.
// ---------------------------------------------------------------------------
__global__ void __launch_bounds__(256) zero_acc_kernel(int n4) {
    int i = blockIdx.x * blockDim.x + threadIdx.x;
    float4 z = make_float4(0.f, 0.f, 0.f, 0.f);
    int stride = gridDim.x * blockDim.x;
    for (; i < n4; i += stride)
        reinterpret_cast<float4*>(g_acc)[i] = z;
}

// ---------------------------------------------------------------------------
// 3xTF32 tensor-core GEMM: C[m][n] = sum_k X[m][k]*W[n][k] + bias[n]
// CTA tile 128x64, 8 warps (warp tile 32x32), k-step 8, double-buffered.
// smem fragment layout per k8 chunk: row r, slot t (0..3), XOR-swizzled
// t' = t ^ (r&3):   float4 = (hi[2t], hi[2t+1], lo[2t], lo[2t+1]).
// k-permutation: mma logical k slot (t,0)->physical 2t, (t,1)->2t+1 on both
// A and B sides (valid: sum over k is permutation invariant).
// ---------------------------------------------------------------------------
#define BM 128
#define BN 64
#define NSTAGES (DIMC / 8)   // 32

__device__ __forceinline__ void gemm_tf32(
    const float* __restrict__ X, int M,
    const float* __restrict__ W,
    const float* __restrict__ Bv,
    float* __restrict__ C,
    int m0, int n0)
{
    __shared__ float4 As[2][BM][4];   // 16 KB
    __shared__ float4 Bs[2][BN][4];   //  8 KB

    int tid  = threadIdx.x;
    int lane = tid & 31;
    int wid  = tid >> 5;
    int wm = (wid & 3) * 32;     // warp m offset in tile
    int wn = (wid >> 2) * 32;    // warp n offset in tile
    int gq = lane >> 2;          // group id 0..7
    int tq = lane & 3;           // thread-in-group 0..3

    // Loader mapping: A: 256 threads, one float4 each (row tid>>1, half tid&1).
    //                 B: threads 0..127, one float4 each.
    int am = tid >> 1;
    int kh = tid & 1;
    bool aval = (m0 + am) < M;
    const float* aptr = X + (size_t)(m0 + am) * DIMC + 4 * kh;
    int bn = (tid >> 1) & 63;
    bool bactive = tid < 128;
    const float* bptr = W + (size_t)(n0 + bn) * DIMC + 4 * kh;

    float acc[2][4][4];
#pragma unroll
    for (int mi = 0; mi < 2; mi++)
#pragma unroll
        for (int ni = 0; ni < 4; ni++)
#pragma unroll
            for (int j = 0; j < 4; j++) acc[mi][ni][j] = 0.f;

    const float4 zf4 = make_float4(0.f, 0.f, 0.f, 0.f);

    // Stage 0 load + commit.
    float4 ra = aval ? *reinterpret_cast<const float4*>(aptr) : zf4;
    float4 rb = bactive ? *reinterpret_cast<const float4*>(bptr) : zf4;

    int t0 = 2 * kh;
    As[0][am][(t0)     ^ (am & 3)] = mk_hilo(ra.x, ra.y);
    As[0][am][(t0 + 1) ^ (am & 3)] = mk_hilo(ra.z, ra.w);
    if (bactive) {
        Bs[0][bn][(t0)     ^ (bn & 3)] = mk_hilo(rb.x, rb.y);
        Bs[0][bn][(t0 + 1) ^ (bn & 3)] = mk_hilo(rb.z, rb.w);
    }
    __syncthreads();

    int buf = 0;
#pragma unroll 1
    for (int st = 0; st < NSTAGES; st++) {
        float4 na, nb;
        if (st + 1 < NSTAGES) {
            int ko = (st + 1) * 8;
            na = aval ? *reinterpret_cast<const float4*>(aptr + ko) : zf4;
            nb = bactive ? *reinterpret_cast<const float4*>(bptr + ko) : zf4;
        }

        // ---- fragments ----
        float4 af0[2], af1[2];   // [mi]: rows g and g+8
#pragma unroll
        for (int mi = 0; mi < 2; mi++) {
            int r0 = wm + mi * 16 + gq;
            af0[mi] = As[buf][r0][tq ^ (r0 & 3)];
            af1[mi] = As[buf][r0 + 8][tq ^ (r0 & 3)];   // (r0+8)&3 == r0&3
        }
        float4 bf[4];
#pragma unroll
        for (int ni = 0; ni < 4; ni++) {
            int rn = wn + ni * 8 + gq;
            bf[ni] = Bs[buf][rn][tq ^ (rn & 3)];
        }

        // ---- 3xTF32 mma: hi*hi, hi*lo, lo*hi ----
#pragma unroll
        for (int mi = 0; mi < 2; mi++) {
            uint32_t a0h = __float_as_uint(af0[mi].x);
            uint32_t a1h = __float_as_uint(af1[mi].x);
            uint32_t a2h = __float_as_uint(af0[mi].y);
            uint32_t a3h = __float_as_uint(af1[mi].y);
            uint32_t a0l = __float_as_uint(af0[mi].z);
            uint32_t a1l = __float_as_uint(af1[mi].z);
            uint32_t a2l = __float_as_uint(af0[mi].w);
            uint32_t a3l = __float_as_uint(af1[mi].w);
#pragma unroll
            for (int ni = 0; ni < 4; ni++) {
                uint32_t b0h = __float_as_uint(bf[ni].x);
                uint32_t b1h = __float_as_uint(bf[ni].y);
                uint32_t b0l = __float_as_uint(bf[ni].z);
                uint32_t b1l = __float_as_uint(bf[ni].w);
                mma_tf32(acc[mi][ni], a0h, a1h, a2h, a3h, b0h, b1h);
                mma_tf32(acc[mi][ni], a0h, a1h, a2h, a3h, b0l, b1l);
                mma_tf32(acc[mi][ni], a0l, a1l, a2l, a3l, b0h, b1h);
            }
        }

        if (st + 1 < NSTAGES) {
            int nb2 = buf ^ 1;
            As[nb2][am][(t0)     ^ (am & 3)] = mk_hilo(na.x, na.y);
            As[nb2][am][(t0 + 1) ^ (am & 3)] = mk_hilo(na.z, na.w);
            if (bactive) {
                Bs[nb2][bn][(t0)     ^ (bn & 3)] = mk_hilo(nb.x, nb.y);
                Bs[nb2][bn][(t0 + 1) ^ (bn & 3)] = mk_hilo(nb.z, nb.w);
            }
            __syncthreads();
            buf = nb2;
        }
    }

    // ---- epilogue: bias + store ----
#pragma unroll
    for (int mi = 0; mi < 2; mi++) {
#pragma unroll
        for (int ni = 0; ni < 4; ni++) {
            int r0 = m0 + wm + mi * 16 + gq;
            int cc = n0 + wn + ni * 8 + 2 * tq;
            float2 bb = *reinterpret_cast<const float2*>(Bv + cc);
            if (r0 < M) {
                float2 o = make_float2(acc[mi][ni][0] + bb.x,
                                       acc[mi][ni][1] + bb.y);
                *reinterpret_cast<float2*>(C + (size_t)r0 * DIMC + cc) = o;
            }
            if (r0 + 8 < M) {
                float2 o = make_float2(acc[mi][ni][2] + bb.x,
                                       acc[mi][ni][3] + bb.y);
                *reinterpret_cast<float2*>(C + (size_t)(r0 + 8) * DIMC + cc) = o;
            }
        }
    }
}

__global__ void __launch_bounds__(256, 2) gemm_qkv_kernel(
    const float* __restrict__ X, int M,
    const float* __restrict__ Wq, const float* __restrict__ bq,
    const float* __restrict__ Wk, const float* __restrict__ bk,
    const float* __restrict__ Wv, const float* __restrict__ bv)
{
    const float* W; const float* B; float* C;
    int z = blockIdx.z;
    if (z == 0)      { W = Wq; B = bq; C = g_q; }
    else if (z == 1) { W = Wk; B = bk; C = g_k; }
    else             { W = Wv; B = bv; C = g_v; }
    gemm_tf32(X, M, W, B, C, blockIdx.y * BM, blockIdx.x * BN);
}

__global__ void __launch_bounds__(256, 2) gemm_out_kernel(
    int M, const float* __restrict__ Wo, const float* __restrict__ bo,
    float* __restrict__ out)
{
    gemm_tf32(g_acc, M, Wo, bo, out, blockIdx.y * BM, blockIdx.x * BN);
}

// ---------------------------------------------------------------------------
// Edge kernel: one warp per edge (round-2 version, known good).
// ---------------------------------------------------------------------------
__device__ __forceinline__ void red_add_v4(float* addr, float4 v) {
    asm volatile("red.global.add.v4.f32 [%0], {%1, %2, %3, %4};"
                 :: "l"(addr), "f"(v.x), "f"(v.y), "f"(v.z), "f"(v.w)
                 : "memory");
}

__global__ void __launch_bounds__(256) edge_kernel(
    const int* __restrict__ src, const int* __restrict__ dst, int E)
{
    int e = (blockIdx.x << 3) + (threadIdx.x >> 5);
    if (e >= E) return;
    int lane = threadIdx.x & 31;

    int s = src[e];
    int d = dst[e];

    const float4* qp = reinterpret_cast<const float4*>(g_q + (size_t)s * DIMC);
    const float4* kp = reinterpret_cast<const float4*>(g_k + (size_t)d * DIMC);

    float4 a0 = qp[lane];
    float4 a1 = qp[lane + 32];
    float4 b0 = kp[lane];
    float4 b1 = kp[lane + 32];

    float p0 = a0.x * b0.x + a0.y * b0.y + a0.z * b0.z + a0.w * b0.w;
    float p1 = a1.x * b1.x + a1.y * b1.y + a1.z * b1.z + a1.w * b1.w;

#pragma unroll
    for (int m = 1; m <= 4; m <<= 1) {
        p0 += __shfl_xor_sync(0xffffffffu, p0, m);
        p1 += __shfl_xor_sync(0xffffffffu, p1, m);
    }

    const float scale = 0.17677669529663687f;   // 1/sqrt(32)
    float sc0 = p0 * scale;
    float sc1 = p1 * scale;

    float sh[8];
#pragma unroll
    for (int h = 0; h < 4; h++) {
        sh[h]     = __shfl_sync(0xffffffffu, sc0, h << 3);
        sh[h + 4] = __shfl_sync(0xffffffffu, sc1, h << 3);
    }

    float mx = sh[0];
#pragma unroll
    for (int h = 1; h < 8; h++) mx = fmaxf(mx, sh[h]);
    float sum = 0.f;
#pragma unroll
    for (int h = 0; h < 8; h++) sum += expf(sh[h] - mx);
    float inv = 1.0f / sum;

    float w0 = expf(sc0 - mx) * inv;
    float w1 = expf(sc1 - mx) * inv;

    const float4* vp = reinterpret_cast<const float4*>(g_v + (size_t)s * DIMC);
    float4 v0 = vp[lane];
    float4 v1 = vp[lane + 32];

    float* op = g_acc + (size_t)d * DIMC;
    red_add_v4(op + (lane << 2),
               make_float4(v0.x * w0, v0.y * w0, v0.z * w0, v0.w * w0));
    red_add_v4(op + ((lane + 32) << 2),
               make_float4(v1.x * w1, v1.y * w1, v1.z * w1, v1.w * w1));
}

// ---------------------------------------------------------------------------
// Launch
// ---------------------------------------------------------------------------
extern "C" void kernel_launch(void* const* d_in, const int* in_sizes, int n_in,
                              void* d_out, int out_size)
{
    const float* x   = (const float*)d_in[0];
    const int*   src = (const int*)  d_in[1];
    const int*   dst = (const int*)  d_in[2];
    const float* Wq  = (const float*)d_in[3];
    const float* bq  = (const float*)d_in[4];
    const float* Wk  = (const float*)d_in[5];
    const float* bk  = (const float*)d_in[6];
    const float* Wv  = (const float*)d_in[7];
    const float* bv  = (const float*)d_in[8];
    const float* Wo  = (const float*)d_in[9];
    const float* bo  = (const float*)d_in[10];
    float* out = (float*)d_out;

    int N = in_sizes[0] / DIMC;
    int E = in_sizes[1];

    int mtiles = (N + BM - 1) / BM;   // 79
    int ntiles = DIMC / BN;           // 4

    // 1) zero accumulator
    int n4 = (N * DIMC) / 4;
    zero_acc_kernel<<<(n4 + 255) / 256, 256>>>(n4);

    // 2) Q/K/V projections (tensor cores, 3xTF32)
    {
        dim3 grid(ntiles, mtiles, 3);
        gemm_qkv_kernel<<<grid, 256>>>(x, N, Wq, bq, Wk, bk, Wv, bv);
    }

    // 3) per-edge attention + scatter
    edge_kernel<<<(E + 7) / 8, 256>>>(src, dst, E);

    // 4) output projection
    {
        dim3 grid(ntiles, mtiles, 1);
        gemm_out_kernel<<<grid, 256>>>(N, Wo, bo, out);
    }
}